// round 9
// baseline (speedup 1.0000x reference)
#include <cuda_runtime.h>

#define S_LEN 256
#define GN 8                   // interpolation grid nodes
#define THREADS 32             // one warp = one batch per block
#define RSTRIDE 68             // floats per quarter-region (64 + 4 pad)

__device__ __forceinline__ float ex2f(float v) {
    float y;
    asm("ex2.approx.ftz.f32 %0, %1;" : "=f"(y) : "f"(v));
    return y;
}

__global__ void __launch_bounds__(THREADS)
pico_transformer_adder_kernel(
    const float* __restrict__ x,
    const float* __restrict__ emb_w,
    const float* __restrict__ emb_b,
    const float* __restrict__ q_w,
    const float* __restrict__ q_b,
    const float* __restrict__ k_w,
    const float* __restrict__ k_b,
    const float* __restrict__ v_w,
    const float* __restrict__ v_b,
    const float* __restrict__ f1_w,
    const float* __restrict__ f1_b,
    const float* __restrict__ f2_w,
    const float* __restrict__ f2_b,
    float* __restrict__ out)
{
    __shared__ __align__(16) float xw [4 * RSTRIDE];   // x values
    __shared__ __align__(16) float x2w[4 * RSTRIDE];   // x^2 values

    const int lane = threadIdx.x;
    const int b    = blockIdx.x;

    // ---- load this batch's 8 x values per lane (coalesced 1KB) ----
    const float4* xr4 = (const float4*)(x + b * S_LEN);
    const float4 va = xr4[lane * 2];
    const float4 vb = xr4[lane * 2 + 1];

    // ---- stage x, x^2 into slabs: quarter r = lane>>3 at r*RSTRIDE ----
    const int base = (lane >> 3) * RSTRIDE + (lane & 7) * 8;
    *(float4*)(xw + base)      = va;
    *(float4*)(xw + base + 4)  = vb;
    *(float4*)(x2w + base)     = make_float4(va.x*va.x, va.y*va.y, va.z*va.z, va.w*va.w);
    *(float4*)(x2w + base + 4) = make_float4(vb.x*vb.x, vb.y*vb.y, vb.z*vb.z, vb.w*vb.w);

    // ---- warp min/max of x ----
    float mx = fmaxf(fmaxf(fmaxf(va.x, va.y), fmaxf(va.z, va.w)),
                     fmaxf(fmaxf(vb.x, vb.y), fmaxf(vb.z, vb.w)));
    float mn = fminf(fminf(fminf(va.x, va.y), fminf(va.z, va.w)),
                     fminf(fminf(vb.x, vb.y), fminf(vb.z, vb.w)));
    #pragma unroll
    for (int o = 16; o; o >>= 1) {
        mx = fmaxf(mx, __shfl_xor_sync(0xffffffffu, mx, o));
        mn = fminf(mn, __shfl_xor_sync(0xffffffffu, mn, o));
    }

    // ---- minimal prologue gating the grid loop: A, C only ----
    const float w0 = emb_w[0], w1 = emb_w[1], w2 = emb_w[2], w3 = emb_w[3];
    const float e0 = emb_b[0], e1 = emb_b[1], e2 = emb_b[2], e3 = emb_b[3];

    float A = 0.f, C = 0.f;
    #pragma unroll
    for (int e = 0; e < 4; ++e) {
        const float qw0 = q_w[e*4+0], qw1 = q_w[e*4+1], qw2 = q_w[e*4+2], qw3 = q_w[e*4+3];
        const float kw0 = k_w[e*4+0], kw1 = k_w[e*4+1], kw2 = k_w[e*4+2], kw3 = k_w[e*4+3];
        const float qa = qw0*w0 + qw1*w1 + qw2*w2 + qw3*w3;
        const float qc = qw0*e0 + qw1*e1 + qw2*e2 + qw3*e3 + q_b[e];
        const float ka = kw0*w0 + kw1*w1 + kw2*w2 + kw3*w3;
        A = fmaf(qa, ka, A);
        C = fmaf(qc, ka, C);
    }
    A *= 0.5f;   // 1/sqrt(d), d=4
    C *= 0.5f;

    // ---- alpha grid (warp-uniform) ----
    const float LOG2E = 1.4426950408889634f;
    const float alo = (A >= 0.f) ? fmaf(A, mn, C) : fmaf(A, mx, C);
    const float ahi = (A >= 0.f) ? fmaf(A, mx, C) : fmaf(A, mn, C);
    const float hstep = fmaxf((ahi - alo) * (1.0f / (float)(GN - 1)), 1e-30f);

    __syncwarp(0xffffffffu);   // smem slabs visible to whole warp

    // ---- grid phase: node g = lane/4, quarter qd = lane&3, 64 j's per lane ----
    const int g  = lane >> 2;
    const int qd = lane & 3;
    const float ag2 = fmaf((float)g, hstep, alo) * LOG2E;
    const float mg  = fmaxf(ag2 * mx, ag2 * mn);   // max achieved by data

    const float4* xp  = (const float4*)(xw  + qd * RSTRIDE);
    const float4* x2p = (const float4*)(x2w + qd * RSTRIDE);

    float s0a = 0.f, s1a = 0.f, s2a = 0.f;
    float s0b = 0.f, s1b = 0.f, s2b = 0.f;
    #pragma unroll 4
    for (int c = 0; c < 16; c += 2) {
        const float4 v = xp[c],   q = x2p[c];
        const float4 u = xp[c+1], r = x2p[c+1];
        float p;
        p = ex2f(fmaf(ag2, v.x, -mg)); s0a += p; s1a = fmaf(p, v.x, s1a); s2a = fmaf(p, q.x, s2a);
        p = ex2f(fmaf(ag2, v.y, -mg)); s0a += p; s1a = fmaf(p, v.y, s1a); s2a = fmaf(p, q.y, s2a);
        p = ex2f(fmaf(ag2, v.z, -mg)); s0a += p; s1a = fmaf(p, v.z, s1a); s2a = fmaf(p, q.z, s2a);
        p = ex2f(fmaf(ag2, v.w, -mg)); s0a += p; s1a = fmaf(p, v.w, s1a); s2a = fmaf(p, q.w, s2a);
        p = ex2f(fmaf(ag2, u.x, -mg)); s0b += p; s1b = fmaf(p, u.x, s1b); s2b = fmaf(p, r.x, s2b);
        p = ex2f(fmaf(ag2, u.y, -mg)); s0b += p; s1b = fmaf(p, u.y, s1b); s2b = fmaf(p, r.y, s2b);
        p = ex2f(fmaf(ag2, u.z, -mg)); s0b += p; s1b = fmaf(p, u.z, s1b); s2b = fmaf(p, r.z, s2b);
        p = ex2f(fmaf(ag2, u.w, -mg)); s0b += p; s1b = fmaf(p, u.w, s1b); s2b = fmaf(p, r.w, s2b);
    }
    float s0 = s0a + s0b, s1 = s1a + s1b, s2 = s2a + s2b;
    #pragma unroll
    for (int o = 1; o < 4; o <<= 1) {
        s0 += __shfl_xor_sync(0xffffffffu, s0, o);
        s1 += __shfl_xor_sync(0xffffffffu, s1, o);
        s2 += __shfl_xor_sync(0xffffffffu, s2, o);
    }

    const float inv = __fdividef(1.0f, s0);
    const float mv  = s1 * inv;                          // m(alpha_g), node g in lanes 4g..4g+3
    const float dvh = fmaf(-mv, mv, s2 * inv) * hstep;   // h * m'(alpha_g)

    // ---- Hermite interpolation at this lane's 8 x values; nodes via shfl.idx ----
    const float inv_h = __fdividef(1.0f, hstep);
    const float xr[8] = {va.x, va.y, va.z, va.w, vb.x, vb.y, vb.z, vb.w};
    float psum = 0.f;
    #pragma unroll
    for (int k = 0; k < 8; ++k) {
        const float u  = (fmaf(A, xr[k], C) - alo) * inv_h;
        int g0 = (int)u;
        g0 = max(0, min(g0, GN - 2));
        const float tt = u - (float)g0;
        const int src = g0 << 2;
        const float m0 = __shfl_sync(0xffffffffu, mv,  src);
        const float m1 = __shfl_sync(0xffffffffu, mv,  src + 4);
        const float d0 = __shfl_sync(0xffffffffu, dvh, src);
        const float d1 = __shfl_sync(0xffffffffu, dvh, src + 4);
        const float t2 = tt * tt, t3 = t2 * tt;
        psum += (2.f*t3 - 3.f*t2 + 1.f) * m0
              + (t3 - 2.f*t2 + tt)      * d0
              + (-2.f*t3 + 3.f*t2)      * m1
              + (t3 - t2)               * d1;
    }
    #pragma unroll
    for (int o = 16; o; o >>= 1) psum += __shfl_xor_sync(0xffffffffu, psum, o);
    const float M = psum * (1.0f / (float)S_LEN);

    // ---- deferred prologue (off the grid-loop critical path): V fold + MLP ----
    const float F2B = f2_b[0];
    float yv = 0.f;
    if (lane < 8) {
        float vaw[4], vcw[4];
        #pragma unroll
        for (int e = 0; e < 4; ++e) {
            const float vw0 = v_w[e*4+0], vw1 = v_w[e*4+1], vw2 = v_w[e*4+2], vw3 = v_w[e*4+3];
            vaw[e] = vw0*w0 + vw1*w1 + vw2*w2 + vw3*w3;
            vcw[e] = vw0*e0 + vw1*e1 + vw2*e2 + vw3*e3 + v_b[e];
        }
        const float4 f1 = ((const float4*)f1_w)[lane];
        const float P = f1.x*vaw[0] + f1.y*vaw[1] + f1.z*vaw[2] + f1.w*vaw[3];
        const float R = f1.x*vcw[0] + f1.y*vcw[1] + f1.z*vcw[2] + f1.w*vcw[3] + f1_b[lane];
        const float F = f2_w[lane];
        yv = F * fmaxf(fmaf(P, M, R), 0.f);
    }
    yv += __shfl_xor_sync(0xffffffffu, yv, 1);
    yv += __shfl_xor_sync(0xffffffffu, yv, 2);
    yv += __shfl_xor_sync(0xffffffffu, yv, 4);
    if (lane == 0) out[b] = yv + F2B;
}

extern "C" void kernel_launch(void* const* d_in, const int* in_sizes, int n_in,
                              void* d_out, int out_size) {
    const float* x     = (const float*)d_in[0];
    const float* emb_w = (const float*)d_in[1];
    const float* emb_b = (const float*)d_in[2];
    const float* q_w   = (const float*)d_in[3];
    const float* q_b   = (const float*)d_in[4];
    const float* k_w   = (const float*)d_in[5];
    const float* k_b   = (const float*)d_in[6];
    const float* v_w   = (const float*)d_in[7];
    const float* v_b   = (const float*)d_in[8];
    const float* f1_w  = (const float*)d_in[9];
    const float* f1_b  = (const float*)d_in[10];
    const float* f2_w  = (const float*)d_in[11];
    const float* f2_b  = (const float*)d_in[12];

    const int B = in_sizes[0] / S_LEN;

    pico_transformer_adder_kernel<<<B, THREADS>>>(
        x, emb_w, emb_b, q_w, q_b, k_w, k_b, v_w, v_b,
        f1_w, f1_b, f2_w, f2_b, (float*)d_out);
}